// round 4
// baseline (speedup 1.0000x reference)
#include <cuda_runtime.h>
#include <cstdint>
#include <cstddef>

// Problem constants
#define DIM   1024
#define BATCH 16
#define SEQL  2048
#define KCONV 3
#define MTOT  (BATCH * SEQL)   // 32768

// ---------------- scratch (static; no allocs allowed) ----------------
__device__ float g_BCx[(size_t)MTOT * 3 * DIM];   // in_proj output (fp32)
__device__ float g_y  [(size_t)MTOT * DIM];       // gated conv output
__device__ float g_xc [(size_t)MTOT * DIM];       // x rounded to tf32
__device__ float g_Wic[(size_t)3 * DIM * DIM];    // Win rounded to tf32
__device__ float g_Woc[(size_t)DIM * DIM];        // Wout rounded to tf32

// ---------------- PTX helpers (all legal on plain sm_103) ----------------
__device__ __forceinline__ float to_tf32(float x) {
    uint32_t b;
    asm("cvt.rna.tf32.f32 %0, %1;" : "=r"(b) : "f"(x));
    return __uint_as_float(b);
}
__device__ __forceinline__ void cp_async16(uint32_t dst, const void* src) {
    asm volatile("cp.async.cg.shared.global [%0], [%1], 16;" :: "r"(dst), "l"(src));
}
#define CP_COMMIT()  asm volatile("cp.async.commit_group;" ::: "memory")
#define CP_WAIT1()   asm volatile("cp.async.wait_group 1;" ::: "memory")

#define SW128(off) ((off) ^ (((off) >> 3) & 0x70))

__device__ __forceinline__ uint32_t smem_u32(const void* p) {
    uint32_t a;
    asm("{ .reg .u64 t; cvta.to.shared.u64 t, %1; cvt.u32.u64 %0, t; }" : "=r"(a) : "l"(p));
    return a;
}

__device__ __forceinline__ void mma_tf32(float* c, const uint32_t* a, const uint32_t* b)
{
    asm volatile(
        "mma.sync.aligned.m16n8k8.row.col.f32.tf32.tf32.f32 "
        "{%0,%1,%2,%3}, {%4,%5,%6,%7}, {%8,%9}, {%0,%1,%2,%3};"
        : "+f"(c[0]), "+f"(c[1]), "+f"(c[2]), "+f"(c[3])
        : "r"(a[0]), "r"(a[1]), "r"(a[2]), "r"(a[3]), "r"(b[0]), "r"(b[1]));
}

// ---------------- GEMM tiling ----------------
#define BM 128
#define BN 128
#define BK 32
#define NSTAGE 2
#define STAGE_BYTES (BM * 128 + BN * 128)       // 16KB + 16KB = 32KB
#define SMEM_DYN (1024 + NSTAGE * STAGE_BYTES)  // 66560 -> 3 CTAs/SM

// fill one operand tile: nrows rows x 32 floats (128B rows, SW128-swizzled)
__device__ __forceinline__ void fill_tile(uint32_t sbase, const float* g, int nrows,
                                          int K, int k0, int tid)
{
    const int nch = nrows * 8;
    for (int idx = tid; idx < nch; idx += 256) {
        int row = idx >> 3;
        int c4  = idx & 7;
        const float* src = g + (size_t)row * K + k0 + c4 * 4;
        uint32_t off = (uint32_t)(row * 128 + c4 * 16);
        cp_async16(sbase + SW128(off), src);
    }
}

// ---------------- tensor-core tf32 GEMM: C[m,n] = sum_k A[m,k]*B[n,k] + bias[n] ----------
__global__ __launch_bounds__(256, 3)
void gemm_tc_tf32(const float* __restrict__ A,
                  const float* __restrict__ B,
                  const float* __restrict__ bias,
                  float* __restrict__ C,
                  int M, int N, int K)
{
    extern __shared__ char smem[];
    const uint32_t sbase = smem_u32(smem);
    const int tid = threadIdx.x;
    const int bm = blockIdx.y * BM;
    const int bn = blockIdx.x * BN;

    // tile region: 1024-aligned within dynamic smem
    const uint32_t tile0 = (sbase + 1023) & ~1023u;
    const uint32_t t0off = tile0 - sbase;

    const float* Ag = A + (size_t)bm * K;
    const float* Bg = B + (size_t)bn * K;
    const int NT = K / BK;   // 32

    const int w = tid >> 5, lane = tid & 31;
    const int wm = (w >> 2) * 64;   // warp M offset (0 or 64)
    const int wn = (w & 3) * 32;    // warp N offset (0..96)

    float acc[4][4][4];
#pragma unroll
    for (int a = 0; a < 4; a++)
#pragma unroll
        for (int b = 0; b < 4; b++)
#pragma unroll
            for (int c = 0; c < 4; c++) acc[a][b][c] = 0.0f;

    // prologue: fill both stages
#pragma unroll
    for (int p = 0; p < NSTAGE; p++) {
        uint32_t sA = tile0 + p * STAGE_BYTES;
        fill_tile(sA, Ag, BM, K, p * BK, tid);
        fill_tile(sA + BM * 128, Bg, BN, K, p * BK, tid);
        CP_COMMIT();
    }

    const char* smemc = smem;

    for (int i = 0; i < NT; i++) {
        const int s = i & 1;
        const uint32_t aoff = t0off + s * STAGE_BYTES;
        const uint32_t boff = aoff + BM * 128;

        CP_WAIT1();          // current stage's group complete (1 newer outstanding)
        __syncthreads();

#pragma unroll
        for (int ks = 0; ks < 4; ks++) {
            const int kb = ks * 32;             // byte offset within 128B row
            uint32_t afr[4][4], bfr[4][2];
#pragma unroll
            for (int mt = 0; mt < 4; mt++) {
                int r = wm + mt * 16 + (lane >> 2);
                uint32_t o = (uint32_t)(r * 128 + kb + (lane & 3) * 4);
                afr[mt][0] = *(const uint32_t*)(smemc + aoff + SW128(o));
                afr[mt][1] = *(const uint32_t*)(smemc + aoff + SW128(o + 8 * 128));
                afr[mt][2] = *(const uint32_t*)(smemc + aoff + SW128(o + 16));
                afr[mt][3] = *(const uint32_t*)(smemc + aoff + SW128(o + 8 * 128 + 16));
            }
#pragma unroll
            for (int nt = 0; nt < 4; nt++) {
                int r = wn + nt * 8 + (lane >> 2);
                uint32_t o = (uint32_t)(r * 128 + kb + (lane & 3) * 4);
                bfr[nt][0] = *(const uint32_t*)(smemc + boff + SW128(o));
                bfr[nt][1] = *(const uint32_t*)(smemc + boff + SW128(o + 16));
            }
#pragma unroll
            for (int mt = 0; mt < 4; mt++)
#pragma unroll
                for (int nt = 0; nt < 4; nt++)
                    mma_tf32(acc[mt][nt], afr[mt], bfr[nt]);
        }

        __syncthreads();     // all warps done reading stage s
        if (i + NSTAGE < NT) {
            const uint32_t sA = tile0 + s * STAGE_BYTES;
            fill_tile(sA, Ag, BM, K, (i + NSTAGE) * BK, tid);
            fill_tile(sA + BM * 128, Bg, BN, K, (i + NSTAGE) * BK, tid);
        }
        CP_COMMIT();         // keep group count invariant (possibly empty)
    }

    // epilogue: direct stores (float2) + bias
#pragma unroll
    for (int mt = 0; mt < 4; mt++) {
#pragma unroll
        for (int nt = 0; nt < 4; nt++) {
            int row0 = bm + wm + mt * 16 + (lane >> 2);
            int col0 = bn + wn + nt * 8 + (lane & 3) * 2;
            float b0 = __ldg(bias + col0), b1 = __ldg(bias + col0 + 1);
            float2 v0 = make_float2(acc[mt][nt][0] + b0, acc[mt][nt][1] + b1);
            float2 v1 = make_float2(acc[mt][nt][2] + b0, acc[mt][nt][3] + b1);
            *(float2*)(C + (size_t)row0 * N + col0) = v0;
            *(float2*)(C + (size_t)(row0 + 8) * N + col0) = v1;
        }
    }
}

// ---------------- elementwise tf32 rounding ----------------
__global__ __launch_bounds__(256)
void cvt_tf32_kernel(const float* __restrict__ in, float* __restrict__ out, int n4)
{
    int i = blockIdx.x * blockDim.x + threadIdx.x;
    if (i < n4) {
        float4 v = reinterpret_cast<const float4*>(in)[i];
        v.x = to_tf32(v.x); v.y = to_tf32(v.y);
        v.z = to_tf32(v.z); v.w = to_tf32(v.w);
        reinterpret_cast<float4*>(out)[i] = v;
    }
}

// ---------------- gate + causal depthwise conv (K=3), tf32-rounded output ----------------
#define LCHUNK 128

__global__ __launch_bounds__(256)
void gate_conv_kernel(const float* __restrict__ BCx,
                      const float* __restrict__ wconv,
                      float* __restrict__ y)
{
    const int d  = blockIdx.x * blockDim.x + threadIdx.x;
    const int b  = blockIdx.y;
    const int l0 = blockIdx.z * LCHUNK;

    const float w0 = wconv[d * KCONV + 0];
    const float w1 = wconv[d * KCONV + 1];
    const float w2 = wconv[d * KCONV + 2];

    const float* base = BCx + (size_t)b * SEQL * 3 * DIM;

    float bxm2 = 0.0f, bxm1 = 0.0f;
    if (l0 >= 2) {
        const float* r = base + (size_t)(l0 - 2) * 3 * DIM;
        bxm2 = r[d] * r[2 * DIM + d];
    }
    if (l0 >= 1) {
        const float* r = base + (size_t)(l0 - 1) * 3 * DIM;
        bxm1 = r[d] * r[2 * DIM + d];
    }

    for (int l = l0; l < l0 + LCHUNK; l++) {
        const float* r = base + (size_t)l * 3 * DIM;
        float bg = r[d];
        float cg = r[DIM + d];
        float xg = r[2 * DIM + d];
        float bx = bg * xg;
        float conv = fmaf(w0, bxm2, fmaf(w1, bxm1, w2 * bx));
        y[((size_t)b * SEQL + l) * DIM + d] = to_tf32(cg * conv);
        bxm2 = bxm1;
        bxm1 = bx;
    }
}

// ---------------------------------------------------------------------------
extern "C" void kernel_launch(void* const* d_in, const int* in_sizes, int n_in,
                              void* d_out, int out_size)
{
    const float* x     = (const float*)d_in[0];
    const float* Win   = (const float*)d_in[1];
    const float* bin_  = (const float*)d_in[2];
    const float* wconv = (const float*)d_in[3];
    const float* Wout  = (const float*)d_in[4];
    const float* bout  = (const float*)d_in[5];
    float* out = (float*)d_out;

    float *BCx, *y, *xc, *Wic, *Woc;
    cudaGetSymbolAddress((void**)&BCx, g_BCx);
    cudaGetSymbolAddress((void**)&y,   g_y);
    cudaGetSymbolAddress((void**)&xc,  g_xc);
    cudaGetSymbolAddress((void**)&Wic, g_Wic);
    cudaGetSymbolAddress((void**)&Woc, g_Woc);

    cudaFuncSetAttribute(gemm_tc_tf32, cudaFuncAttributeMaxDynamicSharedMemorySize, SMEM_DYN);

    const int M = MTOT;

    // round inputs/weights to tf32 (rna)
    {
        int n4 = M * DIM / 4;
        cvt_tf32_kernel<<<(n4 + 255) / 256, 256>>>(x, xc, n4);
        n4 = 3 * DIM * DIM / 4;
        cvt_tf32_kernel<<<(n4 + 255) / 256, 256>>>(Win, Wic, n4);
        n4 = DIM * DIM / 4;
        cvt_tf32_kernel<<<(n4 + 255) / 256, 256>>>(Wout, Woc, n4);
    }

    // GEMM 1: BCx = xc @ Wic^T + bin   (M x 3072, K=1024)
    {
        dim3 grid((3 * DIM) / BN, M / BM);
        gemm_tc_tf32<<<grid, 256, SMEM_DYN>>>(xc, Wic, bin_, BCx, M, 3 * DIM, DIM);
    }

    // gate + causal conv -> y
    {
        dim3 grid(DIM / 256, BATCH, SEQL / LCHUNK);
        gate_conv_kernel<<<grid, 256>>>(BCx, wconv, y);
    }

    // GEMM 2: out = y @ Woc^T + bout  (M x 1024, K=1024)
    {
        dim3 grid(DIM / BN, M / BM);
        gemm_tc_tf32<<<grid, 256, SMEM_DYN>>>(y, Woc, bout, out, M, DIM, DIM);
    }
}

// round 5
// speedup vs baseline: 1.9751x; 1.9751x over previous
#include <cuda_runtime.h>
#include <cstdint>
#include <cstddef>

// Problem constants
#define DIM   1024
#define BATCH 16
#define SEQL  2048
#define KCONV 3
#define MTOT  (BATCH * SEQL)   // 32768

// ---------------- scratch (static; no allocs allowed) ----------------
__device__ float g_BCx[(size_t)MTOT * 3 * DIM];   // in_proj output (fp32)
__device__ float g_y  [(size_t)MTOT * DIM];       // gated conv output
__device__ float g_xc [(size_t)MTOT * DIM];       // x rounded to tf32
__device__ float g_Wic[(size_t)3 * DIM * DIM];    // Win rounded to tf32
__device__ float g_Woc[(size_t)DIM * DIM];        // Wout rounded to tf32

// ---------------- PTX helpers (all legal on plain sm_103) ----------------
__device__ __forceinline__ float to_tf32(float x) {
    uint32_t b;
    asm("cvt.rna.tf32.f32 %0, %1;" : "=r"(b) : "f"(x));
    return __uint_as_float(b);
}
__device__ __forceinline__ void cp_async16(uint32_t dst, const void* src) {
    asm volatile("cp.async.cg.shared.global [%0], [%1], 16;" :: "r"(dst), "l"(src));
}
#define CP_COMMIT()  asm volatile("cp.async.commit_group;" ::: "memory")
#define CP_WAIT1()   asm volatile("cp.async.wait_group 1;" ::: "memory")

#define SW128(off) ((off) ^ (((off) >> 3) & 0x70))

__device__ __forceinline__ uint32_t smem_u32(const void* p) {
    uint32_t a;
    asm("{ .reg .u64 t; cvta.to.shared.u64 t, %1; cvt.u32.u64 %0, t; }" : "=r"(a) : "l"(p));
    return a;
}
__device__ __forceinline__ uint32_t lds32(uint32_t addr) {
    uint32_t v;
    asm volatile("ld.shared.b32 %0, [%1];" : "=r"(v) : "r"(addr));
    return v;
}

__device__ __forceinline__ void mma_tf32(float* c, const uint32_t* a, const uint32_t* b)
{
    asm volatile(
        "mma.sync.aligned.m16n8k8.row.col.f32.tf32.tf32.f32 "
        "{%0,%1,%2,%3}, {%4,%5,%6,%7}, {%8,%9}, {%0,%1,%2,%3};"
        : "+f"(c[0]), "+f"(c[1]), "+f"(c[2]), "+f"(c[3])
        : "r"(a[0]), "r"(a[1]), "r"(a[2]), "r"(a[3]), "r"(b[0]), "r"(b[1]));
}

// ---------------- GEMM tiling ----------------
#define BM 128
#define BN 128
#define BK 32
#define NSTAGE 3
#define STAGE_BYTES (BM * 128 + BN * 128)       // 32KB
#define SMEM_DYN (1024 + NSTAGE * STAGE_BYTES)  // 99328 -> 2 CTAs/SM

// fill one operand tile: nrows rows x 32 floats (128B rows, SW128-swizzled)
__device__ __forceinline__ void fill_tile(uint32_t sbase, const float* g, int nrows,
                                          int K, int k0, int tid)
{
    const int nch = nrows * 8;
    for (int idx = tid; idx < nch; idx += 256) {
        int row = idx >> 3;
        int c4  = idx & 7;
        const float* src = g + (size_t)row * K + k0 + c4 * 4;
        uint32_t off = (uint32_t)(row * 128 + c4 * 16);
        cp_async16(sbase + SW128(off), src);
    }
}

// ---------------- tensor-core tf32 GEMM: C[m,n] = sum_k A[m,k]*B[n,k] + bias[n] ----------
__global__ __launch_bounds__(256, 2)
void gemm_tc_tf32(const float* __restrict__ A,
                  const float* __restrict__ B,
                  const float* __restrict__ bias,
                  float* __restrict__ C,
                  int M, int N, int K)
{
    extern __shared__ char smem[];
    const uint32_t sbase = smem_u32(smem);
    const int tid = threadIdx.x;
    const int bm = blockIdx.y * BM;
    const int bn = blockIdx.x * BN;

    // tile region: 1024-aligned within dynamic smem
    const uint32_t tile0 = (sbase + 1023) & ~1023u;

    const float* Ag = A + (size_t)bm * K;
    const float* Bg = B + (size_t)bn * K;
    const int NT = K / BK;   // 32

    const int w = tid >> 5, lane = tid & 31;
    const int wm = (w >> 2) * 64;   // warp M offset (0 or 64)
    const int wn = (w & 3) * 32;    // warp N offset (0..96)

    // per-thread swizzle decomposition:
    //   fragment row r = <row_block> + (lane>>2); r&7 == lane>>2
    //   addr = stage_base + roff + rowblock*128 + ((kb|half*16) ^ mxor) + 0
    //   where roff = (lane>>2)*128 + (lane&3)*4 (bits 4-6 zero), mxor = (lane>>2)<<4
    const uint32_t roff = (uint32_t)((lane >> 2) * 128 + (lane & 3) * 4);
    const uint32_t mxor = (uint32_t)((lane >> 2) << 4);

    // stage-invariant bases (stage offset added per iteration)
    const uint32_t aW = tile0 + (uint32_t)wm * 128 + roff;             // A ptr base
    const uint32_t bW = tile0 + (uint32_t)(BM * 128) + (uint32_t)wn * 128 + roff;

    float acc[4][4][4];
#pragma unroll
    for (int a = 0; a < 4; a++)
#pragma unroll
        for (int b = 0; b < 4; b++)
#pragma unroll
            for (int c = 0; c < 4; c++) acc[a][b][c] = 0.0f;

    // prologue: fill stages 0,1
#pragma unroll
    for (int p = 0; p < 2; p++) {
        uint32_t sA = tile0 + p * STAGE_BYTES;
        fill_tile(sA, Ag, BM, K, p * BK, tid);
        fill_tile(sA + BM * 128, Bg, BN, K, p * BK, tid);
        CP_COMMIT();
    }

    int s = 0;
    for (int i = 0; i < NT; i++) {
        const uint32_t soff = (uint32_t)s * STAGE_BYTES;

        CP_WAIT1();          // tile i's group complete (tile i+1's may be in flight)
        __syncthreads();     // all warps past iter i-1's reads of stage (i+2)%3

        // prefetch tile i+2 into stage (i+2)%3 (== stage of tile i-1)
        if (i + 2 < NT) {
            int s2 = s + 2; if (s2 >= NSTAGE) s2 -= NSTAGE;
            uint32_t sA = tile0 + (uint32_t)s2 * STAGE_BYTES;
            fill_tile(sA, Ag, BM, K, (i + 2) * BK, tid);
            fill_tile(sA + BM * 128, Bg, BN, K, (i + 2) * BK, tid);
        }
        CP_COMMIT();

        // compute tile i from stage s
#pragma unroll
        for (int ks = 0; ks < 4; ks++) {
            const uint32_t kb = (uint32_t)(ks * 32);
            const uint32_t e0 = kb ^ mxor;          // (kb)     ^ swizzle
            const uint32_t e1 = (kb | 16u) ^ mxor;  // (kb+16)  ^ swizzle
            const uint32_t pa0 = aW + soff + e0;
            const uint32_t pa1 = aW + soff + e1;
            const uint32_t pb0 = bW + soff + e0;
            const uint32_t pb1 = bW + soff + e1;

            uint32_t afr[4][4], bfr[4][2];
#pragma unroll
            for (int mt = 0; mt < 4; mt++) {
                afr[mt][0] = lds32(pa0 + mt * 2048);
                afr[mt][1] = lds32(pa0 + mt * 2048 + 1024);
                afr[mt][2] = lds32(pa1 + mt * 2048);
                afr[mt][3] = lds32(pa1 + mt * 2048 + 1024);
            }
#pragma unroll
            for (int nt = 0; nt < 4; nt++) {
                bfr[nt][0] = lds32(pb0 + nt * 1024);
                bfr[nt][1] = lds32(pb1 + nt * 1024);
            }
#pragma unroll
            for (int mt = 0; mt < 4; mt++)
#pragma unroll
                for (int nt = 0; nt < 4; nt++)
                    mma_tf32(acc[mt][nt], afr[mt], bfr[nt]);
        }

        s++; if (s >= NSTAGE) s -= NSTAGE;
    }

    // epilogue: direct stores (float2) + bias
#pragma unroll
    for (int mt = 0; mt < 4; mt++) {
#pragma unroll
        for (int nt = 0; nt < 4; nt++) {
            int row0 = bm + wm + mt * 16 + (lane >> 2);
            int col0 = bn + wn + nt * 8 + (lane & 3) * 2;
            float b0 = __ldg(bias + col0), b1 = __ldg(bias + col0 + 1);
            float2 v0 = make_float2(acc[mt][nt][0] + b0, acc[mt][nt][1] + b1);
            float2 v1 = make_float2(acc[mt][nt][2] + b0, acc[mt][nt][3] + b1);
            *(float2*)(C + (size_t)row0 * N + col0) = v0;
            *(float2*)(C + (size_t)(row0 + 8) * N + col0) = v1;
        }
    }
}

// ---------------- elementwise tf32 rounding ----------------
__global__ __launch_bounds__(256)
void cvt_tf32_kernel(const float* __restrict__ in, float* __restrict__ out, int n4)
{
    int i = blockIdx.x * blockDim.x + threadIdx.x;
    if (i < n4) {
        float4 v = reinterpret_cast<const float4*>(in)[i];
        v.x = to_tf32(v.x); v.y = to_tf32(v.y);
        v.z = to_tf32(v.z); v.w = to_tf32(v.w);
        reinterpret_cast<float4*>(out)[i] = v;
    }
}

// ---------------- gate + causal depthwise conv (K=3), tf32-rounded output ----------------
#define LCHUNK 128

__global__ __launch_bounds__(256)
void gate_conv_kernel(const float* __restrict__ BCx,
                      const float* __restrict__ wconv,
                      float* __restrict__ y)
{
    const int d  = blockIdx.x * blockDim.x + threadIdx.x;
    const int b  = blockIdx.y;
    const int l0 = blockIdx.z * LCHUNK;

    const float w0 = wconv[d * KCONV + 0];
    const float w1 = wconv[d * KCONV + 1];
    const float w2 = wconv[d * KCONV + 2];

    const float* base = BCx + (size_t)b * SEQL * 3 * DIM;

    float bxm2 = 0.0f, bxm1 = 0.0f;
    if (l0 >= 2) {
        const float* r = base + (size_t)(l0 - 2) * 3 * DIM;
        bxm2 = r[d] * r[2 * DIM + d];
    }
    if (l0 >= 1) {
        const float* r = base + (size_t)(l0 - 1) * 3 * DIM;
        bxm1 = r[d] * r[2 * DIM + d];
    }

    for (int l = l0; l < l0 + LCHUNK; l++) {
        const float* r = base + (size_t)l * 3 * DIM;
        float bg = r[d];
        float cg = r[DIM + d];
        float xg = r[2 * DIM + d];
        float bx = bg * xg;
        float conv = fmaf(w0, bxm2, fmaf(w1, bxm1, w2 * bx));
        y[((size_t)b * SEQL + l) * DIM + d] = to_tf32(cg * conv);
        bxm2 = bxm1;
        bxm1 = bx;
    }
}

// ---------------------------------------------------------------------------
extern "C" void kernel_launch(void* const* d_in, const int* in_sizes, int n_in,
                              void* d_out, int out_size)
{
    const float* x     = (const float*)d_in[0];
    const float* Win   = (const float*)d_in[1];
    const float* bin_  = (const float*)d_in[2];
    const float* wconv = (const float*)d_in[3];
    const float* Wout  = (const float*)d_in[4];
    const float* bout  = (const float*)d_in[5];
    float* out = (float*)d_out;

    float *BCx, *y, *xc, *Wic, *Woc;
    cudaGetSymbolAddress((void**)&BCx, g_BCx);
    cudaGetSymbolAddress((void**)&y,   g_y);
    cudaGetSymbolAddress((void**)&xc,  g_xc);
    cudaGetSymbolAddress((void**)&Wic, g_Wic);
    cudaGetSymbolAddress((void**)&Woc, g_Woc);

    cudaFuncSetAttribute(gemm_tc_tf32, cudaFuncAttributeMaxDynamicSharedMemorySize, SMEM_DYN);

    const int M = MTOT;

    // round inputs/weights to tf32 (rna)
    {
        int n4 = M * DIM / 4;
        cvt_tf32_kernel<<<(n4 + 255) / 256, 256>>>(x, xc, n4);
        n4 = 3 * DIM * DIM / 4;
        cvt_tf32_kernel<<<(n4 + 255) / 256, 256>>>(Win, Wic, n4);
        n4 = DIM * DIM / 4;
        cvt_tf32_kernel<<<(n4 + 255) / 256, 256>>>(Wout, Woc, n4);
    }

    // GEMM 1: BCx = xc @ Wic^T + bin   (M x 3072, K=1024)
    {
        dim3 grid((3 * DIM) / BN, M / BM);
        gemm_tc_tf32<<<grid, 256, SMEM_DYN>>>(xc, Wic, bin_, BCx, M, 3 * DIM, DIM);
    }

    // gate + causal conv -> y
    {
        dim3 grid(DIM / 256, BATCH, SEQL / LCHUNK);
        gate_conv_kernel<<<grid, 256>>>(BCx, wconv, y);
    }

    // GEMM 2: out = y @ Woc^T + bout  (M x 1024, K=1024)
    {
        dim3 grid(DIM / BN, M / BM);
        gemm_tc_tf32<<<grid, 256, SMEM_DYN>>>(y, Woc, bout, out, M, DIM, DIM);
    }
}

// round 7
// speedup vs baseline: 2.9513x; 1.4943x over previous
#include <cuda_runtime.h>
#include <cuda_fp16.h>
#include <cstdint>
#include <cstddef>

// Problem constants
#define DIM   1024
#define BATCH 16
#define SEQL  2048
#define KCONV 3
#define MTOT  (BATCH * SEQL)   // 32768

// ---------------- scratch (static; no allocs allowed) ----------------
__device__ float  g_BCx[(size_t)MTOT * 3 * DIM];               // in_proj out (fp32)
__device__ __align__(16) __half g_yh [(size_t)MTOT * DIM];     // gated conv out (half)
__device__ __align__(16) __half g_xh [(size_t)MTOT * DIM];     // x in half
__device__ __align__(16) __half g_Wih[(size_t)3 * DIM * DIM];  // Win in half
__device__ __align__(16) __half g_Woh[(size_t)DIM * DIM];      // Wout in half

// ---------------- PTX helpers (plain sm_103 legal) ----------------
__device__ __forceinline__ void cp_async16(uint32_t dst, const void* src) {
    asm volatile("cp.async.cg.shared.global [%0], [%1], 16;" :: "r"(dst), "l"(src));
}
#define CP_COMMIT()  asm volatile("cp.async.commit_group;" ::: "memory")
#define CP_WAIT3()   asm volatile("cp.async.wait_group 3;" ::: "memory")

#define SW128(off) ((off) ^ (((off) >> 3) & 0x70))

__device__ __forceinline__ uint32_t smem_u32(const void* p) {
    uint32_t a;
    asm("{ .reg .u64 t; cvta.to.shared.u64 t, %1; cvt.u32.u64 %0, t; }" : "=r"(a) : "l"(p));
    return a;
}
__device__ __forceinline__ uint32_t lds32(uint32_t addr) {
    uint32_t v;
    asm volatile("ld.shared.b32 %0, [%1];" : "=r"(v) : "r"(addr));
    return v;
}

__device__ __forceinline__ void mma_f16(float* c, const uint32_t* a, const uint32_t* b)
{
    asm volatile(
        "mma.sync.aligned.m16n8k16.row.col.f32.f16.f16.f32 "
        "{%0,%1,%2,%3}, {%4,%5,%6,%7}, {%8,%9}, {%0,%1,%2,%3};"
        : "+f"(c[0]), "+f"(c[1]), "+f"(c[2]), "+f"(c[3])
        : "r"(a[0]), "r"(a[1]), "r"(a[2]), "r"(a[3]), "r"(b[0]), "r"(b[1]));
}

// ---------------- GEMM tiling ----------------
#define BM 128
#define BN 128
#define BK 64                                   // 64 halfs = 128B rows
#define NSTAGE 4
#define STAGE_BYTES (BM * 128 + BN * 128)       // 32KB
#define SMEM_DYN (1024 + NSTAGE * STAGE_BYTES)  // 132096 -> 1 CTA/SM

// fill one operand tile: nrows rows x 64 halfs (128B rows, SW128-swizzled)
__device__ __forceinline__ void fill_tile(uint32_t sbase, const __half* g, int nrows,
                                          int K, int k0, int tid)
{
    const int nch = nrows * 8;
    for (int idx = tid; idx < nch; idx += 256) {
        int row = idx >> 3;
        int c4  = idx & 7;
        const __half* src = g + (size_t)row * K + k0 + c4 * 8;
        uint32_t off = (uint32_t)(row * 128 + c4 * 16);
        cp_async16(sbase + SW128(off), src);
    }
}

// ---------------- fp16 tensor-core GEMM: C[m,n] = sum_k A[m,k]*B[n,k] + bias[n] ----------
__global__ __launch_bounds__(256, 1)
void gemm_tc_f16(const __half* __restrict__ A,
                 const __half* __restrict__ B,
                 const float* __restrict__ bias,
                 float* __restrict__ C,
                 int M, int N, int K)
{
    extern __shared__ char smem[];
    const uint32_t sbase = smem_u32(smem);
    const int tid = threadIdx.x;
    const int bm = blockIdx.y * BM;
    const int bn = blockIdx.x * BN;

    const uint32_t tile0 = (sbase + 1023) & ~1023u;

    const __half* Ag = A + (size_t)bm * K;
    const __half* Bg = B + (size_t)bn * K;
    const int NT = K / BK;   // 16

    const int w = tid >> 5, lane = tid & 31;
    const int wm = (w >> 2) * 64;   // warp M offset (0 or 64)
    const int wn = (w & 3) * 32;    // warp N offset (0..96)

    // swizzle decomposition (identical algebra to validated tf32 version):
    const uint32_t roff = (uint32_t)((lane >> 2) * 128 + (lane & 3) * 4);
    const uint32_t mxor = (uint32_t)((lane >> 2) << 4);

    const uint32_t aW = tile0 + (uint32_t)wm * 128 + roff;
    const uint32_t bW = tile0 + (uint32_t)(BM * 128) + (uint32_t)wn * 128 + roff;

    float acc[4][4][4];
#pragma unroll
    for (int a = 0; a < 4; a++)
#pragma unroll
        for (int b = 0; b < 4; b++)
#pragma unroll
            for (int c = 0; c < 4; c++) acc[a][b][c] = 0.0f;

    // prologue: fill all 4 stages (tiles 0..3)
#pragma unroll
    for (int p = 0; p < NSTAGE; p++) {
        uint32_t sA = tile0 + p * STAGE_BYTES;
        fill_tile(sA, Ag, BM, K, p * BK, tid);
        fill_tile(sA + BM * 128, Bg, BN, K, p * BK, tid);
        CP_COMMIT();
    }

    for (int i = 0; i < NT; i++) {
        const int s = i & (NSTAGE - 1);
        const uint32_t soff = (uint32_t)s * STAGE_BYTES;

        CP_WAIT3();          // tile i's group complete (3 newer in flight)
        __syncthreads();

        // compute tile i from stage s: 4 k16-steps
#pragma unroll
        for (int ks = 0; ks < 4; ks++) {
            const uint32_t kb = (uint32_t)(ks * 32);      // 16 halfs per k-step
            const uint32_t e0 = kb ^ mxor;
            const uint32_t e1 = (kb | 16u) ^ mxor;
            const uint32_t pa0 = aW + soff + e0;
            const uint32_t pa1 = aW + soff + e1;
            const uint32_t pb0 = bW + soff + e0;
            const uint32_t pb1 = bW + soff + e1;

            uint32_t afr[4][4], bfr[4][2];
#pragma unroll
            for (int mt = 0; mt < 4; mt++) {
                afr[mt][0] = lds32(pa0 + mt * 2048);           // (r,   k)
                afr[mt][1] = lds32(pa0 + mt * 2048 + 1024);    // (r+8, k)
                afr[mt][2] = lds32(pa1 + mt * 2048);           // (r,   k+8)
                afr[mt][3] = lds32(pa1 + mt * 2048 + 1024);    // (r+8, k+8)
            }
#pragma unroll
            for (int nt = 0; nt < 4; nt++) {
                bfr[nt][0] = lds32(pb0 + nt * 1024);
                bfr[nt][1] = lds32(pb1 + nt * 1024);
            }
#pragma unroll
            for (int mt = 0; mt < 4; mt++)
#pragma unroll
                for (int nt = 0; nt < 4; nt++)
                    mma_f16(acc[mt][nt], afr[mt], bfr[nt]);
        }

        __syncthreads();     // all warps done reading stage s
        if (i + NSTAGE < NT) {
            const uint32_t sA = tile0 + soff;
            fill_tile(sA, Ag, BM, K, (i + NSTAGE) * BK, tid);
            fill_tile(sA + BM * 128, Bg, BN, K, (i + NSTAGE) * BK, tid);
        }
        CP_COMMIT();         // keep group count invariant
    }

    // epilogue: direct stores (float2) + fp32 bias
#pragma unroll
    for (int mt = 0; mt < 4; mt++) {
#pragma unroll
        for (int nt = 0; nt < 4; nt++) {
            int row0 = bm + wm + mt * 16 + (lane >> 2);
            int col0 = bn + wn + nt * 8 + (lane & 3) * 2;
            float b0 = __ldg(bias + col0), b1 = __ldg(bias + col0 + 1);
            float2 v0 = make_float2(acc[mt][nt][0] + b0, acc[mt][nt][1] + b1);
            float2 v1 = make_float2(acc[mt][nt][2] + b0, acc[mt][nt][3] + b1);
            *(float2*)(C + (size_t)row0 * N + col0) = v0;
            *(float2*)(C + (size_t)(row0 + 8) * N + col0) = v1;
        }
    }
}

// ---------------- elementwise fp32 -> half ----------------
__global__ __launch_bounds__(256)
void cvt_f16_kernel(const float* __restrict__ in, __half* __restrict__ out, int n4)
{
    int i = blockIdx.x * blockDim.x + threadIdx.x;
    if (i < n4) {
        float4 v = reinterpret_cast<const float4*>(in)[i];
        __half2 h01 = __floats2half2_rn(v.x, v.y);
        __half2 h23 = __floats2half2_rn(v.z, v.w);
        __half2 pk[2] = { h01, h23 };
        reinterpret_cast<uint2*>(out)[i] = *reinterpret_cast<const uint2*>(pk);
    }
}

// ---------------- gate + causal depthwise conv (K=3), half output ----------------
#define LCHUNK 128

__global__ __launch_bounds__(256)
void gate_conv_kernel(const float* __restrict__ BCx,
                      const float* __restrict__ wconv,
                      __half* __restrict__ y)
{
    const int d  = blockIdx.x * blockDim.x + threadIdx.x;
    const int b  = blockIdx.y;
    const int l0 = blockIdx.z * LCHUNK;

    const float w0 = wconv[d * KCONV + 0];
    const float w1 = wconv[d * KCONV + 1];
    const float w2 = wconv[d * KCONV + 2];

    const float* base = BCx + (size_t)b * SEQL * 3 * DIM;

    float bxm2 = 0.0f, bxm1 = 0.0f;
    if (l0 >= 2) {
        const float* r = base + (size_t)(l0 - 2) * 3 * DIM;
        bxm2 = r[d] * r[2 * DIM + d];
    }
    if (l0 >= 1) {
        const float* r = base + (size_t)(l0 - 1) * 3 * DIM;
        bxm1 = r[d] * r[2 * DIM + d];
    }

    for (int l = l0; l < l0 + LCHUNK; l++) {
        const float* r = base + (size_t)l * 3 * DIM;
        float bg = r[d];
        float cg = r[DIM + d];
        float xg = r[2 * DIM + d];
        float bx = bg * xg;
        float conv = fmaf(w0, bxm2, fmaf(w1, bxm1, w2 * bx));
        y[((size_t)b * SEQL + l) * DIM + d] = __float2half_rn(cg * conv);
        bxm2 = bxm1;
        bxm1 = bx;
    }
}

// ---------------------------------------------------------------------------
extern "C" void kernel_launch(void* const* d_in, const int* in_sizes, int n_in,
                              void* d_out, int out_size)
{
    const float* x     = (const float*)d_in[0];
    const float* Win   = (const float*)d_in[1];
    const float* bin_  = (const float*)d_in[2];
    const float* wconv = (const float*)d_in[3];
    const float* Wout  = (const float*)d_in[4];
    const float* bout  = (const float*)d_in[5];
    float* out = (float*)d_out;

    float *BCx;
    __half *yh, *xh, *Wih, *Woh;
    cudaGetSymbolAddress((void**)&BCx, g_BCx);
    cudaGetSymbolAddress((void**)&yh,  g_yh);
    cudaGetSymbolAddress((void**)&xh,  g_xh);
    cudaGetSymbolAddress((void**)&Wih, g_Wih);
    cudaGetSymbolAddress((void**)&Woh, g_Woh);

    cudaFuncSetAttribute(gemm_tc_f16, cudaFuncAttributeMaxDynamicSharedMemorySize, SMEM_DYN);

    const int M = MTOT;

    // convert inputs/weights to half
    {
        int n4 = M * DIM / 4;
        cvt_f16_kernel<<<(n4 + 255) / 256, 256>>>(x, xh, n4);
        n4 = 3 * DIM * DIM / 4;
        cvt_f16_kernel<<<(n4 + 255) / 256, 256>>>(Win, Wih, n4);
        n4 = DIM * DIM / 4;
        cvt_f16_kernel<<<(n4 + 255) / 256, 256>>>(Wout, Woh, n4);
    }

    // GEMM 1: BCx = xh @ Wih^T + bin   (M x 3072, K=1024)
    {
        dim3 grid((3 * DIM) / BN, M / BM);
        gemm_tc_f16<<<grid, 256, SMEM_DYN>>>(xh, Wih, bin_, BCx, M, 3 * DIM, DIM);
    }

    // gate + causal conv -> yh (half)
    {
        dim3 grid(DIM / 256, BATCH, SEQL / LCHUNK);
        gate_conv_kernel<<<grid, 256>>>(BCx, wconv, yh);
    }

    // GEMM 2: out = yh @ Woh^T + bout  (M x 1024, K=1024)
    {
        dim3 grid(DIM / BN, M / BM);
        gemm_tc_f16<<<grid, 256, SMEM_DYN>>>(yh, Woh, bout, out, M, DIM, DIM);
    }
}

// round 8
// speedup vs baseline: 3.1308x; 1.0608x over previous
#include <cuda_runtime.h>
#include <cuda_fp16.h>
#include <cstdint>
#include <cstddef>

// Problem constants
#define DIM   1024
#define BATCH 16
#define SEQL  2048
#define KCONV 3
#define MTOT  (BATCH * SEQL)   // 32768

// ---------------- scratch (static; no allocs allowed) ----------------
__device__ float  g_BCx[(size_t)MTOT * 3 * DIM];               // in_proj out (fp32)
__device__ __align__(16) __half g_yh [(size_t)MTOT * DIM];     // gated conv out (half)
__device__ __align__(16) __half g_xh [(size_t)MTOT * DIM];     // x in half
__device__ __align__(16) __half g_Wih[(size_t)3 * DIM * DIM];  // Win in half
__device__ __align__(16) __half g_Woh[(size_t)DIM * DIM];      // Wout in half

// ---------------- PTX helpers (plain sm_103 legal) ----------------
__device__ __forceinline__ void cp_async16(uint32_t dst, const void* src) {
    asm volatile("cp.async.cg.shared.global [%0], [%1], 16;" :: "r"(dst), "l"(src));
}
#define CP_COMMIT()  asm volatile("cp.async.commit_group;" ::: "memory")
#define CP_WAIT3()   asm volatile("cp.async.wait_group 3;" ::: "memory")

#define SW128(off) ((off) ^ (((off) >> 3) & 0x70))

__device__ __forceinline__ uint32_t smem_u32(const void* p) {
    uint32_t a;
    asm("{ .reg .u64 t; cvta.to.shared.u64 t, %1; cvt.u32.u64 %0, t; }" : "=r"(a) : "l"(p));
    return a;
}
__device__ __forceinline__ void ldsm_x4(uint32_t* r, uint32_t addr) {
    asm volatile("ldmatrix.sync.aligned.m8n8.x4.shared.b16 {%0,%1,%2,%3}, [%4];"
        : "=r"(r[0]), "=r"(r[1]), "=r"(r[2]), "=r"(r[3]) : "r"(addr));
}
__device__ __forceinline__ void mma_f16(float* c, const uint32_t* a, const uint32_t* b)
{
    asm volatile(
        "mma.sync.aligned.m16n8k16.row.col.f32.f16.f16.f32 "
        "{%0,%1,%2,%3}, {%4,%5,%6,%7}, {%8,%9}, {%0,%1,%2,%3};"
        : "+f"(c[0]), "+f"(c[1]), "+f"(c[2]), "+f"(c[3])
        : "r"(a[0]), "r"(a[1]), "r"(a[2]), "r"(a[3]), "r"(b[0]), "r"(b[1]));
}

// ---------------- GEMM tiling ----------------
#define BM 128
#define BN 128
#define BK 64                                   // 64 halfs = 128B rows
#define NSTAGE 4
#define STAGE_BYTES (BM * 128 + BN * 128)       // 32KB
#define SMEM_DYN (1024 + NSTAGE * STAGE_BYTES)  // 132096 -> 1 CTA/SM

// fill one operand tile: nrows rows x 64 halfs (128B rows, SW128-swizzled)
__device__ __forceinline__ void fill_tile(uint32_t sbase, const __half* g, int nrows,
                                          int K, int k0, int tid)
{
    const int nch = nrows * 8;
    for (int idx = tid; idx < nch; idx += 256) {
        int row = idx >> 3;
        int c4  = idx & 7;
        const __half* src = g + (size_t)row * K + k0 + c4 * 8;
        uint32_t off = (uint32_t)(row * 128 + c4 * 16);
        cp_async16(sbase + SW128(off), src);
    }
}

// ---------------- fp16 tensor-core GEMM: C[m,n] = sum_k A[m,k]*B[n,k] + bias[n] ----------
__global__ __launch_bounds__(256, 1)
void gemm_tc_f16(const __half* __restrict__ A,
                 const __half* __restrict__ B,
                 const float* __restrict__ bias,
                 float* __restrict__ C,
                 int M, int N, int K)
{
    extern __shared__ char smem[];
    const uint32_t sbase = smem_u32(smem);
    const int tid = threadIdx.x;
    const int bm = blockIdx.y * BM;
    const int bn = blockIdx.x * BN;

    const uint32_t tile0 = (sbase + 1023) & ~1023u;

    const __half* Ag = A + (size_t)bm * K;
    const __half* Bg = B + (size_t)bn * K;
    const int NT = K / BK;   // 16

    const int w = tid >> 5, lane = tid & 31;
    const int wm = (w >> 2) * 64;   // warp M offset (0 or 64)
    const int wn = (w & 3) * 32;    // warp N offset (0..96)

    // --- ldmatrix per-lane addressing (SW128 folded) ---
    // A (.x4): matrices {rows r..r+7, r+8..r+15} x {k-bytes +0, +16}
    //   lane i -> row (lane&15), col-half (lane>>4)*16
    const uint32_t a_row  = (uint32_t)(lane & 15);
    const uint32_t a_xor  = (uint32_t)((lane & 7) << 4);
    const uint32_t a_ch   = (uint32_t)((lane >> 4) * 16);
    // B (.x4): matrices {n..n+7 k0, n..n+7 k+16, n+8..n+15 k0, n+8..n+15 k+16}
    //   lane i -> n-row (lane&7) + ((lane>>4)&1)*8, col-half ((lane>>3)&1)*16
    const uint32_t b_row  = (uint32_t)((lane & 7) + ((lane >> 4) & 1) * 8);
    const uint32_t b_xor  = (uint32_t)((lane & 7) << 4);
    const uint32_t b_ch   = (uint32_t)(((lane >> 3) & 1) * 16);

    // stage-invariant address bases
    const uint32_t aBase = tile0 + (uint32_t)wm * 128 + a_row * 128;
    const uint32_t bBase = tile0 + (uint32_t)(BM * 128) + (uint32_t)wn * 128 + b_row * 128;

    float acc[4][4][4];
#pragma unroll
    for (int a = 0; a < 4; a++)
#pragma unroll
        for (int b = 0; b < 4; b++)
#pragma unroll
            for (int c = 0; c < 4; c++) acc[a][b][c] = 0.0f;

    // prologue: fill all 4 stages (tiles 0..3)
#pragma unroll
    for (int p = 0; p < NSTAGE; p++) {
        uint32_t sA = tile0 + p * STAGE_BYTES;
        fill_tile(sA, Ag, BM, K, p * BK, tid);
        fill_tile(sA + BM * 128, Bg, BN, K, p * BK, tid);
        CP_COMMIT();
    }

    uint32_t afr[2][4][4];   // [buf][mt][4 regs]
    uint32_t bfr[2][8];      // [buf][nt*2 + half]

    for (int i = 0; i < NT; i++) {
        const int s = i & (NSTAGE - 1);
        const uint32_t soff = (uint32_t)s * STAGE_BYTES;

        CP_WAIT3();          // tile i's group complete (3 newer in flight)
        __syncthreads();

        const uint32_t aS = aBase + soff;
        const uint32_t bS = bBase + soff;

        // load fragments for ks=0 into buffer 0
        {
            const uint32_t ca = (0u + a_ch) ^ a_xor;
            const uint32_t cb = (0u + b_ch) ^ b_xor;
#pragma unroll
            for (int mt = 0; mt < 4; mt++) ldsm_x4(afr[0][mt], aS + mt * 2048 + ca);
            ldsm_x4(&bfr[0][0], bS + cb);            // nt 0,1
            ldsm_x4(&bfr[0][4], bS + 2048 + cb);     // nt 2,3
        }

#pragma unroll
        for (int ks = 0; ks < 4; ks++) {
            const int cur = ks & 1, nxt = cur ^ 1;
            if (ks < 3) {
                const uint32_t kb = (uint32_t)((ks + 1) * 32);
                const uint32_t ca = (kb + a_ch) ^ a_xor;
                const uint32_t cb = (kb + b_ch) ^ b_xor;
#pragma unroll
                for (int mt = 0; mt < 4; mt++) ldsm_x4(afr[nxt][mt], aS + mt * 2048 + ca);
                ldsm_x4(&bfr[nxt][0], bS + cb);
                ldsm_x4(&bfr[nxt][4], bS + 2048 + cb);
            }
#pragma unroll
            for (int mt = 0; mt < 4; mt++)
#pragma unroll
                for (int nt = 0; nt < 4; nt++)
                    mma_f16(acc[mt][nt], afr[cur][mt], &bfr[cur][nt * 2]);
        }

        __syncthreads();     // all warps done reading stage s
        if (i + NSTAGE < NT) {
            const uint32_t sA = tile0 + soff;
            fill_tile(sA, Ag, BM, K, (i + NSTAGE) * BK, tid);
            fill_tile(sA + BM * 128, Bg, BN, K, (i + NSTAGE) * BK, tid);
        }
        CP_COMMIT();         // keep group count invariant
    }

    // epilogue: direct stores (float2) + fp32 bias
#pragma unroll
    for (int mt = 0; mt < 4; mt++) {
#pragma unroll
        for (int nt = 0; nt < 4; nt++) {
            int row0 = bm + wm + mt * 16 + (lane >> 2);
            int col0 = bn + wn + nt * 8 + (lane & 3) * 2;
            float b0 = __ldg(bias + col0), b1 = __ldg(bias + col0 + 1);
            float2 v0 = make_float2(acc[mt][nt][0] + b0, acc[mt][nt][1] + b1);
            float2 v1 = make_float2(acc[mt][nt][2] + b0, acc[mt][nt][3] + b1);
            *(float2*)(C + (size_t)row0 * N + col0) = v0;
            *(float2*)(C + (size_t)(row0 + 8) * N + col0) = v1;
        }
    }
}

// ---------------- elementwise fp32 -> half ----------------
__global__ __launch_bounds__(256)
void cvt_f16_kernel(const float* __restrict__ in, __half* __restrict__ out, int n4)
{
    int i = blockIdx.x * blockDim.x + threadIdx.x;
    if (i < n4) {
        float4 v = reinterpret_cast<const float4*>(in)[i];
        __half2 h01 = __floats2half2_rn(v.x, v.y);
        __half2 h23 = __floats2half2_rn(v.z, v.w);
        __half2 pk[2] = { h01, h23 };
        reinterpret_cast<uint2*>(out)[i] = *reinterpret_cast<const uint2*>(pk);
    }
}

// ---------------- gate + causal depthwise conv (K=3), half output ----------------
#define LCHUNK 128

__global__ __launch_bounds__(256)
void gate_conv_kernel(const float* __restrict__ BCx,
                      const float* __restrict__ wconv,
                      __half* __restrict__ y)
{
    const int d  = blockIdx.x * blockDim.x + threadIdx.x;
    const int b  = blockIdx.y;
    const int l0 = blockIdx.z * LCHUNK;

    const float w0 = wconv[d * KCONV + 0];
    const float w1 = wconv[d * KCONV + 1];
    const float w2 = wconv[d * KCONV + 2];

    const float* base = BCx + (size_t)b * SEQL * 3 * DIM;

    float bxm2 = 0.0f, bxm1 = 0.0f;
    if (l0 >= 2) {
        const float* r = base + (size_t)(l0 - 2) * 3 * DIM;
        bxm2 = r[d] * r[2 * DIM + d];
    }
    if (l0 >= 1) {
        const float* r = base + (size_t)(l0 - 1) * 3 * DIM;
        bxm1 = r[d] * r[2 * DIM + d];
    }

    for (int l = l0; l < l0 + LCHUNK; l++) {
        const float* r = base + (size_t)l * 3 * DIM;
        float bg = r[d];
        float cg = r[DIM + d];
        float xg = r[2 * DIM + d];
        float bx = bg * xg;
        float conv = fmaf(w0, bxm2, fmaf(w1, bxm1, w2 * bx));
        y[((size_t)b * SEQL + l) * DIM + d] = __float2half_rn(cg * conv);
        bxm2 = bxm1;
        bxm1 = bx;
    }
}

// ---------------------------------------------------------------------------
extern "C" void kernel_launch(void* const* d_in, const int* in_sizes, int n_in,
                              void* d_out, int out_size)
{
    const float* x     = (const float*)d_in[0];
    const float* Win   = (const float*)d_in[1];
    const float* bin_  = (const float*)d_in[2];
    const float* wconv = (const float*)d_in[3];
    const float* Wout  = (const float*)d_in[4];
    const float* bout  = (const float*)d_in[5];
    float* out = (float*)d_out;

    float *BCx;
    __half *yh, *xh, *Wih, *Woh;
    cudaGetSymbolAddress((void**)&BCx, g_BCx);
    cudaGetSymbolAddress((void**)&yh,  g_yh);
    cudaGetSymbolAddress((void**)&xh,  g_xh);
    cudaGetSymbolAddress((void**)&Wih, g_Wih);
    cudaGetSymbolAddress((void**)&Woh, g_Woh);

    cudaFuncSetAttribute(gemm_tc_f16, cudaFuncAttributeMaxDynamicSharedMemorySize, SMEM_DYN);

    const int M = MTOT;

    // convert inputs/weights to half
    {
        int n4 = M * DIM / 4;
        cvt_f16_kernel<<<(n4 + 255) / 256, 256>>>(x, xh, n4);
        n4 = 3 * DIM * DIM / 4;
        cvt_f16_kernel<<<(n4 + 255) / 256, 256>>>(Win, Wih, n4);
        n4 = DIM * DIM / 4;
        cvt_f16_kernel<<<(n4 + 255) / 256, 256>>>(Wout, Woh, n4);
    }

    // GEMM 1: BCx = xh @ Wih^T + bin   (M x 3072, K=1024)
    {
        dim3 grid((3 * DIM) / BN, M / BM);
        gemm_tc_f16<<<grid, 256, SMEM_DYN>>>(xh, Wih, bin_, BCx, M, 3 * DIM, DIM);
    }

    // gate + causal conv -> yh (half)
    {
        dim3 grid(DIM / 256, BATCH, SEQL / LCHUNK);
        gate_conv_kernel<<<grid, 256>>>(BCx, wconv, yh);
    }

    // GEMM 2: out = yh @ Woh^T + bout  (M x 1024, K=1024)
    {
        dim3 grid(DIM / BN, M / BM);
        gemm_tc_f16<<<grid, 256, SMEM_DYN>>>(yh, Woh, bout, out, M, DIM, DIM);
    }
}

// round 9
// speedup vs baseline: 3.7178x; 1.1875x over previous
#include <cuda_runtime.h>
#include <cuda_fp16.h>
#include <cstdint>
#include <cstddef>

// Problem constants
#define DIM   1024
#define BATCH 16
#define SEQL  2048
#define KCONV 3
#define MTOT  (BATCH * SEQL)   // 32768

// ---------------- scratch (static; no allocs allowed) ----------------
__device__ float  g_BCx[(size_t)MTOT * 3 * DIM];               // in_proj out (fp32)
__device__ __align__(16) __half g_yh [(size_t)MTOT * DIM];     // gated conv out (half)
__device__ __align__(16) __half g_xh [(size_t)MTOT * DIM];     // x in half
__device__ __align__(16) __half g_Wih[(size_t)3 * DIM * DIM];  // Win in half
__device__ __align__(16) __half g_Woh[(size_t)DIM * DIM];      // Wout in half

// ---------------- PTX helpers (plain sm_103 legal) ----------------
__device__ __forceinline__ void cp_async16(uint32_t dst, const void* src) {
    asm volatile("cp.async.cg.shared.global [%0], [%1], 16;" :: "r"(dst), "l"(src));
}
#define CP_COMMIT()  asm volatile("cp.async.commit_group;" ::: "memory")
#define CP_WAIT2()   asm volatile("cp.async.wait_group 2;" ::: "memory")

#define SW128(off) ((off) ^ (((off) >> 3) & 0x70))

__device__ __forceinline__ uint32_t smem_u32(const void* p) {
    uint32_t a;
    asm("{ .reg .u64 t; cvta.to.shared.u64 t, %1; cvt.u32.u64 %0, t; }" : "=r"(a) : "l"(p));
    return a;
}
__device__ __forceinline__ void ldsm_x4(uint32_t* r, uint32_t addr) {
    asm volatile("ldmatrix.sync.aligned.m8n8.x4.shared.b16 {%0,%1,%2,%3}, [%4];"
        : "=r"(r[0]), "=r"(r[1]), "=r"(r[2]), "=r"(r[3]) : "r"(addr));
}
__device__ __forceinline__ void mma_f16(float* c, const uint32_t* a, const uint32_t* b)
{
    asm volatile(
        "mma.sync.aligned.m16n8k16.row.col.f32.f16.f16.f32 "
        "{%0,%1,%2,%3}, {%4,%5,%6,%7}, {%8,%9}, {%0,%1,%2,%3};"
        : "+f"(c[0]), "+f"(c[1]), "+f"(c[2]), "+f"(c[3])
        : "r"(a[0]), "r"(a[1]), "r"(a[2]), "r"(a[3]), "r"(b[0]), "r"(b[1]));
}

// ---------------- GEMM tiling ----------------
#define BM 128
#define BN 128
#define BK 64                                   // 64 halfs = 128B rows
#define NSTAGE 3
#define STAGE_BYTES (BM * 128 + BN * 128)       // 32KB
#define SMEM_DYN (1024 + NSTAGE * STAGE_BYTES)  // 99328 -> 2 CTAs/SM

// fill one operand tile: nrows rows x 64 halfs (128B rows, SW128-swizzled)
__device__ __forceinline__ void fill_tile(uint32_t sbase, const __half* g, int nrows,
                                          int K, int k0, int tid)
{
    const int nch = nrows * 8;
    for (int idx = tid; idx < nch; idx += 256) {
        int row = idx >> 3;
        int c4  = idx & 7;
        const __half* src = g + (size_t)row * K + k0 + c4 * 8;
        uint32_t off = (uint32_t)(row * 128 + c4 * 16);
        cp_async16(sbase + SW128(off), src);
    }
}

// ---------------- fp16 tensor-core GEMM: C[m,n] = sum_k A[m,k]*B[n,k] + bias[n] ----------
__global__ __launch_bounds__(256, 2)
void gemm_tc_f16(const __half* __restrict__ A,
                 const __half* __restrict__ B,
                 const float* __restrict__ bias,
                 float* __restrict__ C,
                 int M, int N, int K)
{
    extern __shared__ char smem[];
    const uint32_t sbase = smem_u32(smem);
    const int tid = threadIdx.x;
    const int bm = blockIdx.y * BM;
    const int bn = blockIdx.x * BN;

    const uint32_t tile0 = (sbase + 1023) & ~1023u;

    const __half* Ag = A + (size_t)bm * K;
    const __half* Bg = B + (size_t)bn * K;
    const int NT = K / BK;   // 16

    const int w = tid >> 5, lane = tid & 31;
    const int wm = (w >> 2) * 64;   // warp M offset (0 or 64)
    const int wn = (w & 3) * 32;    // warp N offset (0..96)

    // --- ldmatrix per-lane addressing (SW128 folded) ---
    const uint32_t a_row  = (uint32_t)(lane & 15);
    const uint32_t a_xor  = (uint32_t)((lane & 7) << 4);
    const uint32_t a_ch   = (uint32_t)((lane >> 4) * 16);
    const uint32_t b_row  = (uint32_t)((lane & 7) + ((lane >> 4) & 1) * 8);
    const uint32_t b_xor  = (uint32_t)((lane & 7) << 4);
    const uint32_t b_ch   = (uint32_t)(((lane >> 3) & 1) * 16);

    const uint32_t aBase = tile0 + (uint32_t)wm * 128 + a_row * 128;
    const uint32_t bBase = tile0 + (uint32_t)(BM * 128) + (uint32_t)wn * 128 + b_row * 128;

    float acc[4][4][4];
#pragma unroll
    for (int a = 0; a < 4; a++)
#pragma unroll
        for (int b = 0; b < 4; b++)
#pragma unroll
            for (int c = 0; c < 4; c++) acc[a][b][c] = 0.0f;

    // prologue: fill all 3 stages (tiles 0..2)
#pragma unroll
    for (int p = 0; p < NSTAGE; p++) {
        uint32_t sA = tile0 + p * STAGE_BYTES;
        fill_tile(sA, Ag, BM, K, p * BK, tid);
        fill_tile(sA + BM * 128, Bg, BN, K, p * BK, tid);
        CP_COMMIT();
    }

    int s = 0;
    for (int i = 0; i < NT; i++) {
        const uint32_t soff = (uint32_t)s * STAGE_BYTES;

        CP_WAIT2();          // tile i's group complete (2 newer in flight)
        __syncthreads();

        const uint32_t aS = aBase + soff;
        const uint32_t bS = bBase + soff;

        // compute tile i from stage s: 4 k16-steps, single fragment buffer
#pragma unroll
        for (int ks = 0; ks < 4; ks++) {
            const uint32_t kb = (uint32_t)(ks * 32);
            const uint32_t ca = (kb + a_ch) ^ a_xor;
            const uint32_t cb = (kb + b_ch) ^ b_xor;
            uint32_t afr[4][4], bfr[8];
#pragma unroll
            for (int mt = 0; mt < 4; mt++) ldsm_x4(afr[mt], aS + mt * 2048 + ca);
            ldsm_x4(&bfr[0], bS + cb);            // nt 0,1
            ldsm_x4(&bfr[4], bS + 2048 + cb);     // nt 2,3
#pragma unroll
            for (int mt = 0; mt < 4; mt++)
#pragma unroll
                for (int nt = 0; nt < 4; nt++)
                    mma_f16(acc[mt][nt], afr[mt], &bfr[nt * 2]);
        }

        __syncthreads();     // all warps done reading stage s
        if (i + NSTAGE < NT) {
            const uint32_t sA = tile0 + soff;
            fill_tile(sA, Ag, BM, K, (i + NSTAGE) * BK, tid);
            fill_tile(sA + BM * 128, Bg, BN, K, (i + NSTAGE) * BK, tid);
        }
        CP_COMMIT();         // keep group count invariant

        s++; if (s >= NSTAGE) s -= NSTAGE;
    }

    // epilogue: direct stores (float2) + fp32 bias
#pragma unroll
    for (int mt = 0; mt < 4; mt++) {
#pragma unroll
        for (int nt = 0; nt < 4; nt++) {
            int row0 = bm + wm + mt * 16 + (lane >> 2);
            int col0 = bn + wn + nt * 8 + (lane & 3) * 2;
            float b0 = __ldg(bias + col0), b1 = __ldg(bias + col0 + 1);
            float2 v0 = make_float2(acc[mt][nt][0] + b0, acc[mt][nt][1] + b1);
            float2 v1 = make_float2(acc[mt][nt][2] + b0, acc[mt][nt][3] + b1);
            *(float2*)(C + (size_t)row0 * N + col0) = v0;
            *(float2*)(C + (size_t)(row0 + 8) * N + col0) = v1;
        }
    }
}

// ---------------- elementwise fp32 -> half ----------------
__global__ __launch_bounds__(256)
void cvt_f16_kernel(const float* __restrict__ in, __half* __restrict__ out, int n4)
{
    int i = blockIdx.x * blockDim.x + threadIdx.x;
    if (i < n4) {
        float4 v = reinterpret_cast<const float4*>(in)[i];
        __half2 h01 = __floats2half2_rn(v.x, v.y);
        __half2 h23 = __floats2half2_rn(v.z, v.w);
        __half2 pk[2] = { h01, h23 };
        reinterpret_cast<uint2*>(out)[i] = *reinterpret_cast<const uint2*>(pk);
    }
}

// ---------------- gate + causal depthwise conv (K=3), half output ----------------
#define LCHUNK 128

__global__ __launch_bounds__(256)
void gate_conv_kernel(const float* __restrict__ BCx,
                      const float* __restrict__ wconv,
                      __half* __restrict__ y)
{
    const int d  = blockIdx.x * blockDim.x + threadIdx.x;
    const int b  = blockIdx.y;
    const int l0 = blockIdx.z * LCHUNK;

    const float w0 = wconv[d * KCONV + 0];
    const float w1 = wconv[d * KCONV + 1];
    const float w2 = wconv[d * KCONV + 2];

    const float* base = BCx + (size_t)b * SEQL * 3 * DIM;

    float bxm2 = 0.0f, bxm1 = 0.0f;
    if (l0 >= 2) {
        const float* r = base + (size_t)(l0 - 2) * 3 * DIM;
        bxm2 = r[d] * r[2 * DIM + d];
    }
    if (l0 >= 1) {
        const float* r = base + (size_t)(l0 - 1) * 3 * DIM;
        bxm1 = r[d] * r[2 * DIM + d];
    }

    for (int l = l0; l < l0 + LCHUNK; l++) {
        const float* r = base + (size_t)l * 3 * DIM;
        float bg = r[d];
        float cg = r[DIM + d];
        float xg = r[2 * DIM + d];
        float bx = bg * xg;
        float conv = fmaf(w0, bxm2, fmaf(w1, bxm1, w2 * bx));
        y[((size_t)b * SEQL + l) * DIM + d] = __float2half_rn(cg * conv);
        bxm2 = bxm1;
        bxm1 = bx;
    }
}

// ---------------------------------------------------------------------------
extern "C" void kernel_launch(void* const* d_in, const int* in_sizes, int n_in,
                              void* d_out, int out_size)
{
    const float* x     = (const float*)d_in[0];
    const float* Win   = (const float*)d_in[1];
    const float* bin_  = (const float*)d_in[2];
    const float* wconv = (const float*)d_in[3];
    const float* Wout  = (const float*)d_in[4];
    const float* bout  = (const float*)d_in[5];
    float* out = (float*)d_out;

    float *BCx;
    __half *yh, *xh, *Wih, *Woh;
    cudaGetSymbolAddress((void**)&BCx, g_BCx);
    cudaGetSymbolAddress((void**)&yh,  g_yh);
    cudaGetSymbolAddress((void**)&xh,  g_xh);
    cudaGetSymbolAddress((void**)&Wih, g_Wih);
    cudaGetSymbolAddress((void**)&Woh, g_Woh);

    cudaFuncSetAttribute(gemm_tc_f16, cudaFuncAttributeMaxDynamicSharedMemorySize, SMEM_DYN);

    const int M = MTOT;

    // convert inputs/weights to half
    {
        int n4 = M * DIM / 4;
        cvt_f16_kernel<<<(n4 + 255) / 256, 256>>>(x, xh, n4);
        n4 = 3 * DIM * DIM / 4;
        cvt_f16_kernel<<<(n4 + 255) / 256, 256>>>(Win, Wih, n4);
        n4 = DIM * DIM / 4;
        cvt_f16_kernel<<<(n4 + 255) / 256, 256>>>(Wout, Woh, n4);
    }

    // GEMM 1: BCx = xh @ Wih^T + bin   (M x 3072, K=1024)
    {
        dim3 grid((3 * DIM) / BN, M / BM);
        gemm_tc_f16<<<grid, 256, SMEM_DYN>>>(xh, Wih, bin_, BCx, M, 3 * DIM, DIM);
    }

    // gate + causal conv -> yh (half)
    {
        dim3 grid(DIM / 256, BATCH, SEQL / LCHUNK);
        gate_conv_kernel<<<grid, 256>>>(BCx, wconv, yh);
    }

    // GEMM 2: out = yh @ Woh^T + bout  (M x 1024, K=1024)
    {
        dim3 grid(DIM / BN, M / BM);
        gemm_tc_f16<<<grid, 256, SMEM_DYN>>>(yh, Woh, bout, out, M, DIM, DIM);
    }
}